// round 6
// baseline (speedup 1.0000x reference)
#include <cuda_runtime.h>
#include <cstdint>

#define NN 100000
#define EE 1200000

// Scratch: aggregated messages per node [N, 64].
// Zero-initialized at module load; the MLP kernel re-zeroes its tile every
// call, so the buffer is always zero at kernel_launch entry (graph-replay safe).
__device__ float g_agg[NN * 64];

// ---------------------------------------------------------------------------
// Kernel 1: scatter-add  agg[dst] += node_feat[src] + edge_feat[e]
// 8 threads per edge, 2 float4 chunks per thread (2 independent RED chains).
// ---------------------------------------------------------------------------
__global__ void scatter_kernel(const float* __restrict__ node_feat,
                               const float* __restrict__ edge_feat,
                               const int* __restrict__ ei, int E) {
    int gid = blockIdx.x * blockDim.x + threadIdx.x;
    if (gid >= E * 8) return;
    int e = gid >> 3;
    int c = (gid & 7) * 2;          // chunks c and c+1
    int s = __ldg(ei + e);
    int d = __ldg(ei + E + e);
    const float4* nfp = ((const float4*)node_feat) + (size_t)s * 16 + c;
    const float4* efp = ((const float4*)edge_feat) + (size_t)e * 16 + c;
    float4 nf0 = __ldg(nfp);
    float4 ef0 = __ldg(efp);
    float4 nf1 = __ldg(nfp + 1);
    float4 ef1 = __ldg(efp + 1);
    float4 m0 = make_float4(nf0.x + ef0.x, nf0.y + ef0.y, nf0.z + ef0.z, nf0.w + ef0.w);
    float4 m1 = make_float4(nf1.x + ef1.x, nf1.y + ef1.y, nf1.z + ef1.z, nf1.w + ef1.w);
    float* p = g_agg + (size_t)d * 64 + (c << 2);
    asm volatile("red.global.add.v4.f32 [%0], {%1, %2, %3, %4};"
                 :: "l"(p), "f"(m0.x), "f"(m0.y), "f"(m0.z), "f"(m0.w) : "memory");
    asm volatile("red.global.add.v4.f32 [%0], {%1, %2, %3, %4};"
                 :: "l"(p + 4), "f"(m1.x), "f"(m1.y), "f"(m1.z), "f"(m1.w) : "memory");
}

// ---------------------------------------------------------------------------
// Packed f32x2 helpers
// ---------------------------------------------------------------------------
__device__ __forceinline__ unsigned long long fma2(unsigned long long a,
                                                   unsigned long long b,
                                                   unsigned long long c) {
    unsigned long long d;
    asm("fma.rn.f32x2 %0, %1, %2, %3;" : "=l"(d) : "l"(a), "l"(b), "l"(c));
    return d;
}
__device__ __forceinline__ unsigned long long pack2(float x, float y) {
    unsigned long long d;
    asm("mov.b64 %0, {%1, %2};" : "=l"(d) : "f"(x), "f"(y));
    return d;
}
__device__ __forceinline__ void unpack2(unsigned long long v, float& x, float& y) {
    asm("mov.b64 {%0, %1}, %2;" : "=f"(x), "=f"(y) : "l"(v));
}

// ---------------------------------------------------------------------------
// Kernel 2: fused MLP. BM=128 nodes/block, 256 threads, 2 blocks/SM.
// Also re-zeroes its g_agg tile (overlapped with GEMM1) to restore the
// all-zero invariant for the next graph replay.
// ---------------------------------------------------------------------------
#define BM 128
#define MLP_THREADS 256
#define AT_S 132
#define HS_S 132
#define SM_W1 0
#define SM_AT 8192
#define SM_HS 0
#define SM_W2 16896
#define SM_FLOATS (SM_W2 + 128 * 64)
#define SMEM_BYTES (SM_FLOATS * 4)

__global__ void __launch_bounds__(MLP_THREADS, 2) mlp_kernel(
    const float* __restrict__ W1, const float* __restrict__ b1,
    const float* __restrict__ W2, const float* __restrict__ b2,
    float* __restrict__ out, int N) {
    extern __shared__ float sm[];
    float* W1s = sm + SM_W1;
    float* aT  = sm + SM_AT;
    float* Hs  = sm + SM_HS;
    float* W2s = sm + SM_W2;
    int tid = threadIdx.x;
    int node0 = blockIdx.x * BM;

    // Stage W1 [64][128], W2 [128][64]
#pragma unroll
    for (int i = 0; i < 8; i++) {
        int f = tid + i * 256;
        ((float4*)W1s)[f] = __ldg(((const float4*)W1) + f);
        ((float4*)W2s)[f] = __ldg(((const float4*)W2) + f);
    }
    // Stage agg tile transposed: aT[k][m] = agg[node0+m][k]
#pragma unroll
    for (int i = 0; i < 8; i++) {
        int f = tid + i * 256;          // 0..2047
        int r = f >> 4;                 // node in tile 0..127
        int c4 = f & 15;
        int n = node0 + r;
        float4 v = (n < N) ? __ldg(((const float4*)g_agg) + (size_t)n * 16 + c4)
                           : make_float4(0.f, 0.f, 0.f, 0.f);
        int c = c4 * 4;
        aT[(c + 0) * AT_S + r] = v.x;
        aT[(c + 1) * AT_S + r] = v.y;
        aT[(c + 2) * AT_S + r] = v.z;
        aT[(c + 3) * AT_S + r] = v.w;
    }
    __syncthreads();

    // Re-zero our slice of g_agg (invariant restore). Stores overlap GEMM1.
#pragma unroll
    for (int i = 0; i < 8; i++) {
        int f = tid + i * 256;
        int r = f >> 4;
        int n = node0 + r;
        if (n < N)
            ((float4*)g_agg)[(size_t)n * 16 + (f & 15)] =
                make_float4(0.f, 0.f, 0.f, 0.f);
    }

    // ---------------- GEMM1: H = relu(A @ W1 + b1) ----------------
    int mg = tid & 15;
    int jg = tid >> 4;
    int m0 = mg * 4;
    int j0 = jg * 8;

    unsigned long long acc[8][4];
    {
        float4 blo = __ldg((const float4*)(b1 + j0));
        float4 bhi = __ldg((const float4*)(b1 + j0 + 4));
        unsigned long long bj[4] = { pack2(blo.x, blo.y), pack2(blo.z, blo.w),
                                     pack2(bhi.x, bhi.y), pack2(bhi.z, bhi.w) };
#pragma unroll
        for (int m = 0; m < 8; m++)
#pragma unroll
            for (int p = 0; p < 4; p++) acc[m][p] = bj[p];
    }
#pragma unroll 4
    for (int k = 0; k < 64; k++) {
        float4 a0 = *(const float4*)(aT + k * AT_S + m0);
        float4 a1 = *(const float4*)(aT + k * AT_S + 64 + m0);
        float4 w0 = *(const float4*)(W1s + k * 128 + j0);
        float4 w1 = *(const float4*)(W1s + k * 128 + j0 + 4);
        unsigned long long wv[4] = { pack2(w0.x, w0.y), pack2(w0.z, w0.w),
                                     pack2(w1.x, w1.y), pack2(w1.z, w1.w) };
        float a[8] = { a0.x, a0.y, a0.z, a0.w, a1.x, a1.y, a1.z, a1.w };
#pragma unroll
        for (int m = 0; m < 8; m++) {
            unsigned long long am = pack2(a[m], a[m]);
#pragma unroll
            for (int p = 0; p < 4; p++)
                acc[m][p] = fma2(am, wv[p], acc[m][p]);
        }
    }
    __syncthreads();    // aT/W1s reads done -> safe to alias with Hs

    // ReLU -> Hs[j][m]
#pragma unroll
    for (int p = 0; p < 4; p++) {
#pragma unroll
        for (int h = 0; h < 2; h++) {
            float lo4[4], hi4[4];
#pragma unroll
            for (int m = 0; m < 4; m++) {
                float x, y;
                unpack2(acc[m][p], x, y);
                lo4[m] = fmaxf(h == 0 ? x : y, 0.f);
                unpack2(acc[4 + m][p], x, y);
                hi4[m] = fmaxf(h == 0 ? x : y, 0.f);
            }
            int j = j0 + 2 * p + h;
            *(float4*)(Hs + j * HS_S + m0)      = make_float4(lo4[0], lo4[1], lo4[2], lo4[3]);
            *(float4*)(Hs + j * HS_S + 64 + m0) = make_float4(hi4[0], hi4[1], hi4[2], hi4[3]);
        }
    }
    __syncthreads();

    // ---------------- GEMM2: out = H @ W2 + b2  (all 256 threads) ----------------
    {
        int mg2 = tid & 31;
        int jg2 = tid >> 5;
        int m02 = mg2 * 4;
        int j02 = jg2 * 8;

        unsigned long long acc2[4][4];
        {
            float4 blo = __ldg((const float4*)(b2 + j02));
            float4 bhi = __ldg((const float4*)(b2 + j02 + 4));
            unsigned long long bj[4] = { pack2(blo.x, blo.y), pack2(blo.z, blo.w),
                                         pack2(bhi.x, bhi.y), pack2(bhi.z, bhi.w) };
#pragma unroll
            for (int m = 0; m < 4; m++)
#pragma unroll
                for (int p = 0; p < 4; p++) acc2[m][p] = bj[p];
        }
#pragma unroll 4
        for (int k = 0; k < 128; k++) {
            float4 hv = *(const float4*)(Hs + k * HS_S + m02);
            float4 w0 = *(const float4*)(W2s + k * 64 + j02);
            float4 w1 = *(const float4*)(W2s + k * 64 + j02 + 4);
            unsigned long long wv[4] = { pack2(w0.x, w0.y), pack2(w0.z, w0.w),
                                         pack2(w1.x, w1.y), pack2(w1.z, w1.w) };
            float h4[4] = { hv.x, hv.y, hv.z, hv.w };
#pragma unroll
            for (int m = 0; m < 4; m++) {
                unsigned long long hm = pack2(h4[m], h4[m]);
#pragma unroll
                for (int p = 0; p < 4; p++)
                    acc2[m][p] = fma2(hm, wv[p], acc2[m][p]);
            }
        }
#pragma unroll
        for (int m = 0; m < 4; m++) {
            int n = node0 + m02 + m;
            if (n < N) {
                float4 v0, v1;
                unpack2(acc2[m][0], v0.x, v0.y);
                unpack2(acc2[m][1], v0.z, v0.w);
                unpack2(acc2[m][2], v1.x, v1.y);
                unpack2(acc2[m][3], v1.z, v1.w);
                *(float4*)(out + (size_t)n * 64 + j02)     = v0;
                *(float4*)(out + (size_t)n * 64 + j02 + 4) = v1;
            }
        }
    }
}

// ---------------------------------------------------------------------------
// Launch: scatter -> MLP (MLP restores the zero invariant on g_agg)
// ---------------------------------------------------------------------------
extern "C" void kernel_launch(void* const* d_in, const int* in_sizes, int n_in,
                              void* d_out, int out_size) {
    const float* node_feat = (const float*)d_in[0];
    const float* edge_feat = (const float*)d_in[1];
    const int*   ei        = (const int*)d_in[2];
    const float* W1        = (const float*)d_in[3];
    const float* b1        = (const float*)d_in[4];
    const float* W2        = (const float*)d_in[5];
    const float* b2        = (const float*)d_in[6];
    float* out = (float*)d_out;

    int N = in_sizes[0] / 64;   // 100000
    int E = in_sizes[2] / 2;    // 1200000

    cudaFuncSetAttribute(mlp_kernel, cudaFuncAttributeMaxDynamicSharedMemorySize,
                         SMEM_BYTES);

    scatter_kernel<<<(E * 8 + 255) / 256, 256>>>(node_feat, edge_feat, ei, E);
    mlp_kernel<<<(N + BM - 1) / BM, MLP_THREADS, SMEM_BYTES>>>(W1, b1, W2, b2, out, N);
}

// round 7
// speedup vs baseline: 1.0554x; 1.0554x over previous
#include <cuda_runtime.h>
#include <cstdint>

#define NN 100000
#define EE 1200000

// Scratch: aggregated messages per node [N, 64].
// Zero-initialized at module load; the MLP kernel re-zeroes its tile every
// call, so the buffer is always zero at kernel_launch entry (graph-replay safe).
__device__ float g_agg[NN * 64];

// ---------------------------------------------------------------------------
// Kernel 1: scatter-add  agg[dst] += node_feat[src] + edge_feat[e]
// 16 threads per edge, one float4 chunk each (round-5 best variant).
// ---------------------------------------------------------------------------
__global__ void scatter_kernel(const float* __restrict__ node_feat,
                               const float* __restrict__ edge_feat,
                               const int* __restrict__ ei, int E) {
    int gid = blockIdx.x * blockDim.x + threadIdx.x;
    if (gid >= E * 16) return;
    int e = gid >> 4;
    int c = gid & 15;
    int s = __ldg(ei + e);
    int d = __ldg(ei + E + e);
    float4 nf = __ldg(((const float4*)node_feat) + s * 16 + c);
    float4 ef = __ldg(((const float4*)edge_feat) + (size_t)e * 16 + c);
    float4 m = make_float4(nf.x + ef.x, nf.y + ef.y, nf.z + ef.z, nf.w + ef.w);
    float* p = g_agg + (size_t)d * 64 + (c << 2);
    asm volatile("red.global.add.v4.f32 [%0], {%1, %2, %3, %4};"
                 :: "l"(p), "f"(m.x), "f"(m.y), "f"(m.z), "f"(m.w)
                 : "memory");
}

// ---------------------------------------------------------------------------
// Packed f32x2 helpers
// ---------------------------------------------------------------------------
__device__ __forceinline__ unsigned long long fma2(unsigned long long a,
                                                   unsigned long long b,
                                                   unsigned long long c) {
    unsigned long long d;
    asm("fma.rn.f32x2 %0, %1, %2, %3;" : "=l"(d) : "l"(a), "l"(b), "l"(c));
    return d;
}
__device__ __forceinline__ unsigned long long pack2(float x, float y) {
    unsigned long long d;
    asm("mov.b64 %0, {%1, %2};" : "=l"(d) : "f"(x), "f"(y));
    return d;
}
__device__ __forceinline__ void unpack2(unsigned long long v, float& x, float& y) {
    asm("mov.b64 {%0, %1}, %2;" : "=f"(x), "=f"(y) : "l"(v));
}

// ---------------------------------------------------------------------------
// Kernel 2: fused MLP. BM=128 nodes/block, 256 threads, 2 blocks/SM.
// Software-pipelined k-loops: prefetch k+1 operands during k's FMAs.
// ---------------------------------------------------------------------------
#define BM 128
#define MLP_THREADS 256
#define AT_S 132
#define HS_S 132
#define SM_W1 0
#define SM_AT 8192
#define SM_HS 0
#define SM_W2 16896
#define SM_FLOATS (SM_W2 + 128 * 64)
#define SMEM_BYTES (SM_FLOATS * 4)

__device__ __forceinline__ void gemm1_step(
    unsigned long long (&acc)[8][4],
    const float4& a0, const float4& a1, const float4& w0, const float4& w1) {
    unsigned long long wv[4] = { pack2(w0.x, w0.y), pack2(w0.z, w0.w),
                                 pack2(w1.x, w1.y), pack2(w1.z, w1.w) };
    float a[8] = { a0.x, a0.y, a0.z, a0.w, a1.x, a1.y, a1.z, a1.w };
#pragma unroll
    for (int m = 0; m < 8; m++) {
        unsigned long long am = pack2(a[m], a[m]);
#pragma unroll
        for (int p = 0; p < 4; p++)
            acc[m][p] = fma2(am, wv[p], acc[m][p]);
    }
}

__device__ __forceinline__ void gemm2_step(
    unsigned long long (&acc)[4][4],
    const float4& hv, const float4& w0, const float4& w1) {
    unsigned long long wv[4] = { pack2(w0.x, w0.y), pack2(w0.z, w0.w),
                                 pack2(w1.x, w1.y), pack2(w1.z, w1.w) };
    float h4[4] = { hv.x, hv.y, hv.z, hv.w };
#pragma unroll
    for (int m = 0; m < 4; m++) {
        unsigned long long hm = pack2(h4[m], h4[m]);
#pragma unroll
        for (int p = 0; p < 4; p++)
            acc[m][p] = fma2(hm, wv[p], acc[m][p]);
    }
}

__global__ void __launch_bounds__(MLP_THREADS, 2) mlp_kernel(
    const float* __restrict__ W1, const float* __restrict__ b1,
    const float* __restrict__ W2, const float* __restrict__ b2,
    float* __restrict__ out, int N) {
    extern __shared__ float sm[];
    float* W1s = sm + SM_W1;
    float* aT  = sm + SM_AT;
    float* Hs  = sm + SM_HS;
    float* W2s = sm + SM_W2;
    int tid = threadIdx.x;
    int node0 = blockIdx.x * BM;

    // Stage W1 [64][128], W2 [128][64]
#pragma unroll
    for (int i = 0; i < 8; i++) {
        int f = tid + i * 256;
        ((float4*)W1s)[f] = __ldg(((const float4*)W1) + f);
        ((float4*)W2s)[f] = __ldg(((const float4*)W2) + f);
    }
    // Stage agg tile transposed: aT[k][m] = agg[node0+m][k]
#pragma unroll
    for (int i = 0; i < 8; i++) {
        int f = tid + i * 256;
        int r = f >> 4;
        int c4 = f & 15;
        int n = node0 + r;
        float4 v = (n < N) ? __ldg(((const float4*)g_agg) + (size_t)n * 16 + c4)
                           : make_float4(0.f, 0.f, 0.f, 0.f);
        int c = c4 * 4;
        aT[(c + 0) * AT_S + r] = v.x;
        aT[(c + 1) * AT_S + r] = v.y;
        aT[(c + 2) * AT_S + r] = v.z;
        aT[(c + 3) * AT_S + r] = v.w;
    }
    __syncthreads();

    // Re-zero our slice of g_agg (invariant restore); overlaps GEMM1.
#pragma unroll
    for (int i = 0; i < 8; i++) {
        int f = tid + i * 256;
        int r = f >> 4;
        int n = node0 + r;
        if (n < N)
            ((float4*)g_agg)[(size_t)n * 16 + (f & 15)] =
                make_float4(0.f, 0.f, 0.f, 0.f);
    }

    // ---------------- GEMM1: H = relu(A @ W1 + b1) ----------------
    int mg = tid & 15;
    int jg = tid >> 4;
    int m0 = mg * 4;
    int j0 = jg * 8;

    unsigned long long acc[8][4];
    {
        float4 blo = __ldg((const float4*)(b1 + j0));
        float4 bhi = __ldg((const float4*)(b1 + j0 + 4));
        unsigned long long bj[4] = { pack2(blo.x, blo.y), pack2(blo.z, blo.w),
                                     pack2(bhi.x, bhi.y), pack2(bhi.z, bhi.w) };
#pragma unroll
        for (int m = 0; m < 8; m++)
#pragma unroll
            for (int p = 0; p < 4; p++) acc[m][p] = bj[p];
    }
    {
        float4 a0 = *(const float4*)(aT + m0);
        float4 a1 = *(const float4*)(aT + 64 + m0);
        float4 w0 = *(const float4*)(W1s + j0);
        float4 w1 = *(const float4*)(W1s + j0 + 4);
#pragma unroll 4
        for (int k = 0; k < 63; k++) {
            float4 ca0 = a0, ca1 = a1, cw0 = w0, cw1 = w1;
            a0 = *(const float4*)(aT + (k + 1) * AT_S + m0);
            a1 = *(const float4*)(aT + (k + 1) * AT_S + 64 + m0);
            w0 = *(const float4*)(W1s + (k + 1) * 128 + j0);
            w1 = *(const float4*)(W1s + (k + 1) * 128 + j0 + 4);
            gemm1_step(acc, ca0, ca1, cw0, cw1);
        }
        gemm1_step(acc, a0, a1, w0, w1);   // k = 63
    }
    __syncthreads();    // aT/W1s reads done -> safe to alias with Hs

    // ReLU -> Hs[j][m]
#pragma unroll
    for (int p = 0; p < 4; p++) {
#pragma unroll
        for (int h = 0; h < 2; h++) {
            float lo4[4], hi4[4];
#pragma unroll
            for (int m = 0; m < 4; m++) {
                float x, y;
                unpack2(acc[m][p], x, y);
                lo4[m] = fmaxf(h == 0 ? x : y, 0.f);
                unpack2(acc[4 + m][p], x, y);
                hi4[m] = fmaxf(h == 0 ? x : y, 0.f);
            }
            int j = j0 + 2 * p + h;
            *(float4*)(Hs + j * HS_S + m0)      = make_float4(lo4[0], lo4[1], lo4[2], lo4[3]);
            *(float4*)(Hs + j * HS_S + 64 + m0) = make_float4(hi4[0], hi4[1], hi4[2], hi4[3]);
        }
    }
    __syncthreads();

    // ---------------- GEMM2: out = H @ W2 + b2  (all 256 threads) ----------------
    {
        int mg2 = tid & 31;
        int jg2 = tid >> 5;
        int m02 = mg2 * 4;
        int j02 = jg2 * 8;

        unsigned long long acc2[4][4];
        {
            float4 blo = __ldg((const float4*)(b2 + j02));
            float4 bhi = __ldg((const float4*)(b2 + j02 + 4));
            unsigned long long bj[4] = { pack2(blo.x, blo.y), pack2(blo.z, blo.w),
                                         pack2(bhi.x, bhi.y), pack2(bhi.z, bhi.w) };
#pragma unroll
            for (int m = 0; m < 4; m++)
#pragma unroll
                for (int p = 0; p < 4; p++) acc2[m][p] = bj[p];
        }
        float4 hv = *(const float4*)(Hs + m02);
        float4 w0 = *(const float4*)(W2s + j02);
        float4 w1 = *(const float4*)(W2s + j02 + 4);
#pragma unroll 4
        for (int k = 0; k < 127; k++) {
            float4 chv = hv, cw0 = w0, cw1 = w1;
            hv = *(const float4*)(Hs + (k + 1) * HS_S + m02);
            w0 = *(const float4*)(W2s + (k + 1) * 64 + j02);
            w1 = *(const float4*)(W2s + (k + 1) * 64 + j02 + 4);
            gemm2_step(acc2, chv, cw0, cw1);
        }
        gemm2_step(acc2, hv, w0, w1);      // k = 127

#pragma unroll
        for (int m = 0; m < 4; m++) {
            int n = node0 + m02 + m;
            if (n < N) {
                float4 v0, v1;
                unpack2(acc2[m][0], v0.x, v0.y);
                unpack2(acc2[m][1], v0.z, v0.w);
                unpack2(acc2[m][2], v1.x, v1.y);
                unpack2(acc2[m][3], v1.z, v1.w);
                *(float4*)(out + (size_t)n * 64 + j02)     = v0;
                *(float4*)(out + (size_t)n * 64 + j02 + 4) = v1;
            }
        }
    }
}

// ---------------------------------------------------------------------------
// Launch: scatter -> MLP (MLP restores the zero invariant on g_agg)
// ---------------------------------------------------------------------------
extern "C" void kernel_launch(void* const* d_in, const int* in_sizes, int n_in,
                              void* d_out, int out_size) {
    const float* node_feat = (const float*)d_in[0];
    const float* edge_feat = (const float*)d_in[1];
    const int*   ei        = (const int*)d_in[2];
    const float* W1        = (const float*)d_in[3];
    const float* b1        = (const float*)d_in[4];
    const float* W2        = (const float*)d_in[5];
    const float* b2        = (const float*)d_in[6];
    float* out = (float*)d_out;

    int N = in_sizes[0] / 64;   // 100000
    int E = in_sizes[2] / 2;    // 1200000

    cudaFuncSetAttribute(mlp_kernel, cudaFuncAttributeMaxDynamicSharedMemorySize,
                         SMEM_BYTES);

    scatter_kernel<<<(E * 16 + 255) / 256, 256>>>(node_feat, edge_feat, ei, E);
    mlp_kernel<<<(N + BM - 1) / BM, MLP_THREADS, SMEM_BYTES>>>(W1, b1, W2, b2, out, N);
}